// round 14
// baseline (speedup 1.0000x reference)
#include <cuda_runtime.h>
#include <cuda_fp16.h>
#include <cstdint>

#define D_MODEL 1024
#define D_DICT  16384
#define NTOK    8192
#define TOPK    32

#define CAND_CAP 256
#define NARROW   96
#define CAND2    160
#define THR_SIG  2.55f

// ---------------- scratch (static device globals; no allocations) ----------------
__device__ uint8_t g_x8[NTOK * D_MODEL];           // 8 MB   x in e4m3
__device__ uint8_t g_w8[(size_t)D_DICT * D_MODEL]; // 16 MB  W_enc in e4m3
__device__ __half  g_wt[(size_t)D_DICT * D_MODEL]; // 32 MB  W_dec^T in fp16 [f][d]
__device__ float   g_thr[NTOK];
__device__ unsigned g_cand[NTOK * CAND_CAP];       // (fp16 abs bits << 16) | col
__device__ int     g_cnt[NTOK];
__device__ int     g_selidx[NTOK * TOPK];
__device__ float   g_selval[NTOK * TOPK];

// ---------------- fp8 convert helper ----------------
__device__ __forceinline__ unsigned short e4m3x2(float hi, float lo) {
    unsigned short r;
    asm("cvt.rn.satfinite.e4m3x2.f32 %0, %1, %2;" : "=h"(r) : "f"(hi), "f"(lo));
    return r;
}

// ---------------- utility kernels ----------------
// W_enc fp32 -> e4m3
__global__ void cvtw_kernel(const float4* __restrict__ s, int n4) {
    unsigned* d = reinterpret_cast<unsigned*>(g_w8);
    for (int i = blockIdx.x * blockDim.x + threadIdx.x; i < n4; i += gridDim.x * blockDim.x) {
        float4 v = s[i];
        unsigned lo = e4m3x2(v.y, v.x);
        unsigned hi = e4m3x2(v.w, v.z);
        d[i] = lo | (hi << 16);
    }
}

// per-row threshold + fused x fp32 -> e4m3 + g_cnt reset
__global__ void rownorm_kernel(const float* __restrict__ x) {
    int row = blockIdx.x * 8 + (threadIdx.x >> 5);
    int lane = threadIdx.x & 31;
    const float4* xr = reinterpret_cast<const float4*>(x + (size_t)row * D_MODEL);
    unsigned* x8 = reinterpret_cast<unsigned*>(g_x8 + (size_t)row * D_MODEL);
    float ss = 0.f;
#pragma unroll
    for (int j = 0; j < 8; ++j) {
        float4 v = xr[lane + j * 32];
        ss += v.x * v.x + v.y * v.y + v.z * v.z + v.w * v.w;
        unsigned lo = e4m3x2(v.y, v.x);
        unsigned hi = e4m3x2(v.w, v.z);
        x8[lane + j * 32] = lo | (hi << 16);
    }
#pragma unroll
    for (int off = 16; off; off >>= 1) ss += __shfl_down_sync(0xffffffffu, ss, off);
    if (lane == 0) {
        g_thr[row] = THR_SIG * sqrtf(ss) * (1.0f / 32.0f);
        g_cnt[row] = 0;
    }
}

// W_dec [1024][16384] fp32 -> g_wt [16384][1024] fp16
__global__ void transpose_kernel(const float* __restrict__ src) {
    __shared__ float tile[32][33];
    int fx = blockIdx.x * 32 + threadIdx.x;
    int dy = blockIdx.y * 32 + threadIdx.y;
#pragma unroll
    for (int j = 0; j < 32; j += 8)
        tile[threadIdx.y + j][threadIdx.x] = src[(size_t)(dy + j) * D_DICT + fx];
    __syncthreads();
    int dx = blockIdx.y * 32 + threadIdx.x;
    int fy = blockIdx.x * 32 + threadIdx.y;
#pragma unroll
    for (int j = 0; j < 32; j += 8)
        g_wt[(size_t)(fy + j) * D_MODEL + dx] = __float2half_rn(tile[threadIdx.x][threadIdx.y + j]);
}

// ---------------- fp8 mma.sync encoder GEMM (128x128 CTA, 64x32 warp) ----------------
#define BM 128
#define BN 128
#define BKB 128   // K bytes per chunk (128 fp8 elements)
#define BKPB 144  // padded K byte stride

__device__ __forceinline__ void cp16(uint32_t s, const void* g) {
    asm volatile("cp.async.cg.shared.global [%0], [%1], 16;\n" :: "r"(s), "l"(g));
}
__device__ __forceinline__ void cp_commit() { asm volatile("cp.async.commit_group;\n"); }
__device__ __forceinline__ void cp_wait0()  { asm volatile("cp.async.wait_group 0;\n"); }
__device__ __forceinline__ void cp_wait1()  { asm volatile("cp.async.wait_group 1;\n"); }

__device__ __forceinline__ void ldsm4(uint32_t& r0, uint32_t& r1, uint32_t& r2, uint32_t& r3, uint32_t a) {
    asm volatile("ldmatrix.sync.aligned.m8n8.x4.shared.b16 {%0,%1,%2,%3}, [%4];\n"
                 : "=r"(r0), "=r"(r1), "=r"(r2), "=r"(r3) : "r"(a));
}
__device__ __forceinline__ void mma_fp8(float* c, const uint32_t* a, const uint32_t* b) {
    asm volatile("mma.sync.aligned.m16n8k32.row.col.f32.e4m3.e4m3.f32 "
                 "{%0,%1,%2,%3},{%4,%5,%6,%7},{%8,%9},{%0,%1,%2,%3};\n"
                 : "+f"(c[0]), "+f"(c[1]), "+f"(c[2]), "+f"(c[3])
                 : "r"(a[0]), "r"(a[1]), "r"(a[2]), "r"(a[3]), "r"(b[0]), "r"(b[1]));
}

__device__ __forceinline__ void push_cand(int row, int col, float v, float th) {
    if (fabsf(v) >= th) {
        unsigned hb = __half_as_ushort(__float2half_rn(fabsf(v)));
        unsigned key = (hb << 16) | (unsigned)col;
        int p = atomicAdd(&g_cnt[row], 1);
        if (p < CAND_CAP) g_cand[row * CAND_CAP + p] = key;
    }
}

__global__ void __launch_bounds__(256, 2) gemm_enc_kernel(const float* __restrict__ b_enc,
                                                          float* __restrict__ zout) {
    extern __shared__ uint8_t smem[];
    uint8_t* As = smem;                      // [2][BM][BKPB]
    uint8_t* Bs = smem + 2 * BM * BKPB;      // [2][BN][BKPB]
    uint32_t As_u = (uint32_t)__cvta_generic_to_shared(As);
    uint32_t Bs_u = (uint32_t)__cvta_generic_to_shared(Bs);

    const int tid  = threadIdx.x;
    const int lane = tid & 31, warp = tid >> 5;
    const int wm = warp >> 2;
    const int wn = warp & 3;
    const int m0 = blockIdx.y * BM;
    const int n0 = blockIdx.x * BN;

    float acc[4][4][4];
#pragma unroll
    for (int i = 0; i < 4; ++i)
#pragma unroll
        for (int j = 0; j < 4; ++j)
#pragma unroll
            for (int k = 0; k < 4; ++k) acc[i][j][k] = 0.f;

    // ---- precomputed bases (all mainloop addresses = base + immediate) ----
    const int a_row  = wm * 64 + (lane & 15);
    const int a_colb = (lane >> 4) * 16;
    const int b_row  = wn * 32 + (lane & 7) + ((lane >> 4) & 1) * 8;
    const int b_colb = ((lane >> 3) & 1) * 16;
    const int l_row = tid >> 3;
    const int l_cb  = (tid & 7) * 16;

    const uint32_t aS0 = As_u + a_row * BKPB + a_colb;            // ldsm A base, buf0
    const uint32_t aS1 = aS0 + BM * BKPB;                         // buf1
    const uint32_t bS0 = Bs_u + b_row * BKPB + b_colb;
    const uint32_t bS1 = bS0 + BM * BKPB;
    const uint32_t aD0 = As_u + l_row * BKPB + l_cb;              // cp.async dst base, buf0
    const uint32_t aD1 = aD0 + BM * BKPB;
    const uint32_t bD0 = Bs_u + l_row * BKPB + l_cb;
    const uint32_t bD1 = bD0 + BM * BKPB;
    const uint8_t* gAt = g_x8 + (size_t)(m0 + l_row) * D_MODEL + l_cb;
    const uint8_t* gBt = g_w8 + (size_t)(n0 + l_row) * D_MODEL + l_cb;

    auto fill = [&](uint32_t aD, uint32_t bD, int kn) {
#pragma unroll
        for (int it = 0; it < 4; ++it) {
            cp16(aD + it * 32 * BKPB, gAt + kn + (size_t)it * 32 * D_MODEL);
            cp16(bD + it * 32 * BKPB, gBt + kn + (size_t)it * 32 * D_MODEL);
        }
    };
    auto compute = [&](uint32_t aS, uint32_t bS) {
#pragma unroll
        for (int ks = 0; ks < 4; ++ks) {
            const int kb = ks * 32;
            uint32_t a[4][4];
#pragma unroll
            for (int mi = 0; mi < 4; ++mi)
                ldsm4(a[mi][0], a[mi][1], a[mi][2], a[mi][3], aS + mi * 16 * BKPB + kb);
            uint32_t b[4][2];
#pragma unroll
            for (int p = 0; p < 2; ++p) {
                uint32_t r0, r1, r2, r3;
                ldsm4(r0, r1, r2, r3, bS + p * 16 * BKPB + kb);
                b[2 * p][0] = r0; b[2 * p][1] = r1;
                b[2 * p + 1][0] = r2; b[2 * p + 1][1] = r3;
            }
#pragma unroll
            for (int mi = 0; mi < 4; ++mi)
#pragma unroll
                for (int ni = 0; ni < 4; ++ni)
                    mma_fp8(acc[mi][ni], a[mi], b[ni]);
        }
    };

    // prologue: K chunk 0 -> buf0
    fill(aD0, bD0, 0);
    cp_commit();

    // mainloop: kt unrolled x2 so the buffer index is compile-time everywhere
#pragma unroll
    for (int kt2 = 0; kt2 < 8; kt2 += 2) {
        // phase A: prefetch chunk kt2+1 -> buf1, compute buf0
        fill(aD1, bD1, (kt2 + 1) * BKB);
        cp_commit();
        cp_wait1();
        __syncthreads();
        compute(aS0, bS0);
        __syncthreads();
        // phase B: prefetch chunk kt2+2 -> buf0 (if any), compute buf1
        if (kt2 + 2 < 8) {
            fill(aD0, bD0, (kt2 + 2) * BKB);
            cp_commit();
            cp_wait1();
        } else {
            cp_wait0();
        }
        __syncthreads();
        compute(aS1, bS1);
        __syncthreads();
    }

    // epilogue: + bias, threshold, push candidates, and stream-zero this CTA's zout tile
    const int g = lane >> 2, t = lane & 3;
    const float2 z2 = make_float2(0.f, 0.f);
#pragma unroll
    for (int mi = 0; mi < 4; ++mi) {
        int r0 = m0 + wm * 64 + mi * 16 + g;
        float th0 = g_thr[r0], th1 = g_thr[r0 + 8];
#pragma unroll
        for (int ni = 0; ni < 4; ++ni) {
            int c = n0 + wn * 32 + ni * 8 + t * 2;
            float2 bb = *reinterpret_cast<const float2*>(b_enc + c);
            push_cand(r0,     c,     acc[mi][ni][0] + bb.x, th0);
            push_cand(r0,     c + 1, acc[mi][ni][1] + bb.y, th0);
            push_cand(r0 + 8, c,     acc[mi][ni][2] + bb.x, th1);
            push_cand(r0 + 8, c + 1, acc[mi][ni][3] + bb.y, th1);
            __stcs(reinterpret_cast<float2*>(zout + (size_t)r0 * D_DICT + c), z2);
            __stcs(reinterpret_cast<float2*>(zout + (size_t)(r0 + 8) * D_DICT + c), z2);
        }
    }
}

// ---------------- narrow (top-96 by key) + exact fp32 recompute + warp top-32 ----------------
__global__ void __launch_bounds__(256) exact_kernel(const float* __restrict__ x,
                                                    const float* __restrict__ W,
                                                    const float* __restrict__ b_enc,
                                                    float* __restrict__ zout) {
    const int row = blockIdx.x, tid = threadIdx.x;
    const int lane = tid & 31, warp = tid >> 5;
    __shared__ float xs[D_MODEL];
    __shared__ unsigned skeys[CAND_CAP];
    __shared__ int hist[256];
    __shared__ int cidx[CAND2];
    __shared__ float cval[CAND2];
    __shared__ int ssel[TOPK];
    __shared__ int s_cut, s_scnt;

    reinterpret_cast<float4*>(xs)[tid] =
        reinterpret_cast<const float4*>(x + (size_t)row * D_MODEL)[tid];
    int cnt = min(g_cnt[row], CAND_CAP);
    hist[tid] = 0;
    if (tid == 0) s_scnt = 0;
    for (int i = tid; i < cnt; i += 256) skeys[i] = g_cand[row * CAND_CAP + i];
    __syncthreads();

    for (int i = tid; i < cnt; i += 256) {
        int bin = (int)((skeys[i] >> 16) - 0x4000u) >> 4;
        bin = max(0, min(bin, 255));
        atomicAdd(&hist[bin], 1);
    }
    __syncthreads();
#pragma unroll
    for (int off = 1; off < 256; off <<= 1) {
        int v = (tid + off < 256) ? hist[tid + off] : 0;
        __syncthreads();
        hist[tid] += v;
        __syncthreads();
    }
    int need = min(NARROW, cnt);
    if (hist[tid] >= need && (tid == 255 || hist[tid + 1] < need)) s_cut = tid;
    __syncthreads();
    int cut = s_cut;

    for (int i = tid; i < cnt; i += 256) {
        int bin = (int)((skeys[i] >> 16) - 0x4000u) >> 4;
        bin = max(0, min(bin, 255));
        if (bin >= cut) {
            int p = atomicAdd(&s_scnt, 1);
            if (p < CAND2) cidx[p] = (int)(skeys[i] & 0xFFFFu);
        }
    }
    __syncthreads();
    int cnt2 = min(s_scnt, CAND2);

    const float4* xs4 = reinterpret_cast<const float4*>(xs);
    for (int c = warp; c < cnt2; c += 8) {
        int f = cidx[c];
        const float4* w4 = reinterpret_cast<const float4*>(W + (size_t)f * D_MODEL);
        float a0 = 0.f, a1 = 0.f;
#pragma unroll
        for (int j = 0; j < 8; j += 2) {
            float4 wv = w4[lane + j * 32], xv = xs4[lane + j * 32];
            a0 += wv.x * xv.x; a0 += wv.y * xv.y; a0 += wv.z * xv.z; a0 += wv.w * xv.w;
            float4 wv2 = w4[lane + (j + 1) * 32], xv2 = xs4[lane + (j + 1) * 32];
            a1 += wv2.x * xv2.x; a1 += wv2.y * xv2.y; a1 += wv2.z * xv2.z; a1 += wv2.w * xv2.w;
        }
        float a = a0 + a1;
#pragma unroll
        for (int off = 16; off; off >>= 1) a += __shfl_down_sync(0xffffffffu, a, off);
        if (lane == 0) cval[c] = a + b_enc[f];
    }
    __syncthreads();

    if (warp == 0) {
        float v[5]; int id[5];
#pragma unroll
        for (int j = 0; j < 5; ++j) {
            int i = lane + j * 32;
            if (i < cnt2) { v[j] = fabsf(cval[i]); id[j] = i; }
            else          { v[j] = -1.f;           id[j] = -1; }
        }
        for (int it = 0; it < TOPK; ++it) {
            float mv = v[0]; int ms = 0;
#pragma unroll
            for (int j = 1; j < 5; ++j)
                if (v[j] > mv) { mv = v[j]; ms = j; }
            float bv = mv; int bl = lane;
#pragma unroll
            for (int off = 16; off; off >>= 1) {
                float ov = __shfl_xor_sync(0xffffffffu, bv, off);
                int   ol = __shfl_xor_sync(0xffffffffu, bl, off);
                if (ov > bv || (ov == bv && ol < bl)) { bv = ov; bl = ol; }
            }
            if (lane == bl) { ssel[it] = id[ms]; v[ms] = -1.f; }
        }
    }
    __syncthreads();

    if (tid < TOPK) {
        int s = ssel[tid];
        if (s >= 0) {
            int f = cidx[s]; float vv = cval[s];
            zout[(size_t)row * D_DICT + f] = vv;
            g_selidx[row * TOPK + tid] = f;
            g_selval[row * TOPK + tid] = vv;
        } else {
            g_selidx[row * TOPK + tid] = 0;
            g_selval[row * TOPK + tid] = 0.f;
        }
    }
}

// ---------------- sparse decoder (fp16 weights) ----------------
__global__ void decode_kernel(const float* __restrict__ b_dec, float* __restrict__ recon) {
    const int row = blockIdx.x, tid = threadIdx.x;
    __shared__ int sif[TOPK];
    __shared__ float sv[TOPK];
    if (tid < TOPK) { sif[tid] = g_selidx[row * TOPK + tid]; sv[tid] = g_selval[row * TOPK + tid]; }
    __syncthreads();
    float4 acc = reinterpret_cast<const float4*>(b_dec)[tid];
    const uint2* wt2 = reinterpret_cast<const uint2*>(g_wt);
#pragma unroll 4
    for (int s = 0; s < TOPK; ++s) {
        float v = sv[s]; int f = sif[s];
        uint2 w = wt2[(size_t)f * (D_MODEL / 4) + tid];
        float2 f01 = __half22float2(*reinterpret_cast<__half2*>(&w.x));
        float2 f23 = __half22float2(*reinterpret_cast<__half2*>(&w.y));
        acc.x += v * f01.x; acc.y += v * f01.y; acc.z += v * f23.x; acc.w += v * f23.y;
    }
    reinterpret_cast<float4*>(recon + (size_t)row * D_MODEL)[tid] = acc;
}

// ---------------- launch ----------------
extern "C" void kernel_launch(void* const* d_in, const int* in_sizes, int n_in,
                              void* d_out, int out_size) {
    const float* x     = (const float*)d_in[0];
    const float* W_enc = (const float*)d_in[1];
    const float* b_enc = (const float*)d_in[2];
    const float* W_dec = (const float*)d_in[3];
    const float* b_dec = (const float*)d_in[4];
    float* recon = (float*)d_out;
    float* zout  = recon + (size_t)NTOK * D_MODEL;

    const int GEMM_SMEM = 2 * (BM + BN) * BKPB;  // 73728 B
    cudaFuncSetAttribute(gemm_enc_kernel, cudaFuncAttributeMaxDynamicSharedMemorySize, GEMM_SMEM);

    rownorm_kernel<<<NTOK / 8, 256>>>(x);                                          // 1 (also resets g_cnt)
    cvtw_kernel<<<2048, 256>>>(reinterpret_cast<const float4*>(W_enc),
                               D_DICT * D_MODEL / 4);                              // 2
    transpose_kernel<<<dim3(D_DICT / 32, D_MODEL / 32), dim3(32, 8)>>>(W_dec);     // 3
    gemm_enc_kernel<<<dim3(D_DICT / BN, NTOK / BM), 256, GEMM_SMEM>>>(b_enc, zout);// 4 (zeros zout tile-wise)
    exact_kernel<<<NTOK, 256>>>(x, W_enc, b_enc, zout);                            // 5
    decode_kernel<<<NTOK, 256>>>(b_dec, recon);                                    // 6
}

// round 16
// speedup vs baseline: 1.0893x; 1.0893x over previous
#include <cuda_runtime.h>
#include <cuda_fp16.h>
#include <cstdint>

#define D_MODEL 1024
#define D_DICT  16384
#define NTOK    8192
#define TOPK    32

#define CAND_CAP 256
#define NARROW   64
#define CAND2    160
#define THR_SIG  2.55f

// ---------------- scratch (static device globals; no allocations) ----------------
__device__ uint8_t g_x8[NTOK * D_MODEL];           // 8 MB   x in e4m3
__device__ uint8_t g_w8[(size_t)D_DICT * D_MODEL]; // 16 MB  W_enc in e4m3
__device__ __half  g_wt[(size_t)D_DICT * D_MODEL]; // 32 MB  W_dec^T in fp16 [f][d]
__device__ float   g_thr[NTOK];
__device__ unsigned g_cand[NTOK * CAND_CAP];       // (fp16 abs bits << 16) | col
__device__ int     g_cnt[NTOK];
__device__ int     g_selidx[NTOK * TOPK];
__device__ float   g_selval[NTOK * TOPK];

// ---------------- fp8 convert helper ----------------
__device__ __forceinline__ unsigned short e4m3x2(float hi, float lo) {
    unsigned short r;
    asm("cvt.rn.satfinite.e4m3x2.f32 %0, %1, %2;" : "=h"(r) : "f"(hi), "f"(lo));
    return r;
}

// ---------------- utility kernels ----------------
// W_enc fp32 -> e4m3
__global__ void cvtw_kernel(const float4* __restrict__ s, int n4) {
    unsigned* d = reinterpret_cast<unsigned*>(g_w8);
    for (int i = blockIdx.x * blockDim.x + threadIdx.x; i < n4; i += gridDim.x * blockDim.x) {
        float4 v = s[i];
        unsigned lo = e4m3x2(v.y, v.x);
        unsigned hi = e4m3x2(v.w, v.z);
        d[i] = lo | (hi << 16);
    }
}

// per-row threshold + fused x fp32 -> e4m3 + g_cnt reset
__global__ void rownorm_kernel(const float* __restrict__ x) {
    int row = blockIdx.x * 8 + (threadIdx.x >> 5);
    int lane = threadIdx.x & 31;
    const float4* xr = reinterpret_cast<const float4*>(x + (size_t)row * D_MODEL);
    unsigned* x8 = reinterpret_cast<unsigned*>(g_x8 + (size_t)row * D_MODEL);
    float ss = 0.f;
#pragma unroll
    for (int j = 0; j < 8; ++j) {
        float4 v = xr[lane + j * 32];
        ss += v.x * v.x + v.y * v.y + v.z * v.z + v.w * v.w;
        unsigned lo = e4m3x2(v.y, v.x);
        unsigned hi = e4m3x2(v.w, v.z);
        x8[lane + j * 32] = lo | (hi << 16);
    }
#pragma unroll
    for (int off = 16; off; off >>= 1) ss += __shfl_down_sync(0xffffffffu, ss, off);
    if (lane == 0) {
        g_thr[row] = THR_SIG * sqrtf(ss) * (1.0f / 32.0f);
        g_cnt[row] = 0;
    }
}

// W_dec [1024][16384] fp32 -> g_wt [16384][1024] fp16
__global__ void transpose_kernel(const float* __restrict__ src) {
    __shared__ float tile[32][33];
    int fx = blockIdx.x * 32 + threadIdx.x;
    int dy = blockIdx.y * 32 + threadIdx.y;
#pragma unroll
    for (int j = 0; j < 32; j += 8)
        tile[threadIdx.y + j][threadIdx.x] = src[(size_t)(dy + j) * D_DICT + fx];
    __syncthreads();
    int dx = blockIdx.y * 32 + threadIdx.x;
    int fy = blockIdx.x * 32 + threadIdx.y;
#pragma unroll
    for (int j = 0; j < 32; j += 8)
        g_wt[(size_t)(fy + j) * D_MODEL + dx] = __float2half_rn(tile[threadIdx.x][threadIdx.y + j]);
}

// ---------------- fp8 mma.sync encoder GEMM (128x128 CTA, 64x32 warp) ----------------
#define BM 128
#define BN 128
#define BKB 128   // K bytes per chunk (128 fp8 elements)
#define BKPB 144  // padded K byte stride

__device__ __forceinline__ void cp16(uint32_t s, const void* g) {
    asm volatile("cp.async.cg.shared.global [%0], [%1], 16;\n" :: "r"(s), "l"(g));
}
__device__ __forceinline__ void cp_commit() { asm volatile("cp.async.commit_group;\n"); }
__device__ __forceinline__ void cp_wait0()  { asm volatile("cp.async.wait_group 0;\n"); }

__device__ __forceinline__ void ldsm4(uint32_t& r0, uint32_t& r1, uint32_t& r2, uint32_t& r3, uint32_t a) {
    asm volatile("ldmatrix.sync.aligned.m8n8.x4.shared.b16 {%0,%1,%2,%3}, [%4];\n"
                 : "=r"(r0), "=r"(r1), "=r"(r2), "=r"(r3) : "r"(a));
}
__device__ __forceinline__ void mma_fp8(float* c, const uint32_t* a, const uint32_t* b) {
    asm volatile("mma.sync.aligned.m16n8k32.row.col.f32.e4m3.e4m3.f32 "
                 "{%0,%1,%2,%3},{%4,%5,%6,%7},{%8,%9},{%0,%1,%2,%3};\n"
                 : "+f"(c[0]), "+f"(c[1]), "+f"(c[2]), "+f"(c[3])
                 : "r"(a[0]), "r"(a[1]), "r"(a[2]), "r"(a[3]), "r"(b[0]), "r"(b[1]));
}

__device__ __forceinline__ void push_cand(int row, int col, float v, float th) {
    if (fabsf(v) >= th) {
        unsigned hb = __half_as_ushort(__float2half_rn(fabsf(v)));
        unsigned key = (hb << 16) | (unsigned)col;
        int p = atomicAdd(&g_cnt[row], 1);
        if (p < CAND_CAP) g_cand[row * CAND_CAP + p] = key;
    }
}

__global__ void __launch_bounds__(256, 2) gemm_enc_kernel(const float* __restrict__ b_enc,
                                                          float* __restrict__ zout) {
    extern __shared__ uint8_t smem[];
    uint8_t* As = smem;                      // [2][BM][BKPB]
    uint8_t* Bs = smem + 2 * BM * BKPB;      // [2][BN][BKPB]
    uint32_t As_u = (uint32_t)__cvta_generic_to_shared(As);
    uint32_t Bs_u = (uint32_t)__cvta_generic_to_shared(Bs);

    const int tid  = threadIdx.x;
    const int lane = tid & 31, warp = tid >> 5;
    const int wm = warp >> 2;
    const int wn = warp & 3;
    const int m0 = blockIdx.y * BM;
    const int n0 = blockIdx.x * BN;

    float acc[4][4][4];
#pragma unroll
    for (int i = 0; i < 4; ++i)
#pragma unroll
        for (int j = 0; j < 4; ++j)
#pragma unroll
            for (int k = 0; k < 4; ++k) acc[i][j][k] = 0.f;

    const int a_row  = wm * 64 + (lane & 15);
    const int a_colb = (lane >> 4) * 16;
    const int b_row  = wn * 32 + (lane & 7) + ((lane >> 4) & 1) * 8;
    const int b_colb = ((lane >> 3) & 1) * 16;
    const int l_row = tid >> 3;
    const int l_cb  = (tid & 7) * 16;

    const uint32_t aS0 = As_u + a_row * BKPB + a_colb;
    const uint32_t aS1 = aS0 + BM * BKPB;
    const uint32_t bS0 = Bs_u + b_row * BKPB + b_colb;
    const uint32_t bS1 = bS0 + BM * BKPB;
    const uint32_t aD0 = As_u + l_row * BKPB + l_cb;
    const uint32_t aD1 = aD0 + BM * BKPB;
    const uint32_t bD0 = Bs_u + l_row * BKPB + l_cb;
    const uint32_t bD1 = bD0 + BM * BKPB;
    const uint8_t* gAt = g_x8 + (size_t)(m0 + l_row) * D_MODEL + l_cb;
    const uint8_t* gBt = g_w8 + (size_t)(n0 + l_row) * D_MODEL + l_cb;

    auto fill = [&](uint32_t aD, uint32_t bD, int kn) {
#pragma unroll
        for (int it = 0; it < 4; ++it) {
            cp16(aD + it * 32 * BKPB, gAt + kn + (size_t)it * 32 * D_MODEL);
            cp16(bD + it * 32 * BKPB, gBt + kn + (size_t)it * 32 * D_MODEL);
        }
    };
    auto compute = [&](uint32_t aS, uint32_t bS) {
#pragma unroll
        for (int ks = 0; ks < 4; ++ks) {
            const int kb = ks * 32;
            uint32_t a[4][4];
#pragma unroll
            for (int mi = 0; mi < 4; ++mi)
                ldsm4(a[mi][0], a[mi][1], a[mi][2], a[mi][3], aS + mi * 16 * BKPB + kb);
            uint32_t b[4][2];
#pragma unroll
            for (int p = 0; p < 2; ++p) {
                uint32_t r0, r1, r2, r3;
                ldsm4(r0, r1, r2, r3, bS + p * 16 * BKPB + kb);
                b[2 * p][0] = r0; b[2 * p][1] = r1;
                b[2 * p + 1][0] = r2; b[2 * p + 1][1] = r3;
            }
#pragma unroll
            for (int mi = 0; mi < 4; ++mi)
#pragma unroll
                for (int ni = 0; ni < 4; ++ni)
                    mma_fp8(acc[mi][ni], a[mi], b[ni]);
        }
    };

    // prologue: K chunk 0 -> buf0
    fill(aD0, bD0, 0);
    cp_commit();

    // mainloop: ONE barrier per tile.
    // barrier at iter kt orders compute(kt-1) (on buf kt-1) before fill(kt+1)
    // overwrites that same buffer; cp_wait0 ensures tile kt has landed.
#pragma unroll
    for (int kt = 0; kt < 8; ++kt) {
        cp_wait0();
        __syncthreads();
        if (kt + 1 < 8) {
            if (kt & 1) fill(aD0, bD0, (kt + 1) * BKB);
            else        fill(aD1, bD1, (kt + 1) * BKB);
            cp_commit();
        }
        if (kt & 1) compute(aS1, bS1);
        else        compute(aS0, bS0);
    }

    // epilogue: + bias, threshold, push candidates, and stream-zero this CTA's zout tile
    const int g = lane >> 2, t = lane & 3;
    const float2 z2 = make_float2(0.f, 0.f);
#pragma unroll
    for (int mi = 0; mi < 4; ++mi) {
        int r0 = m0 + wm * 64 + mi * 16 + g;
        float th0 = g_thr[r0], th1 = g_thr[r0 + 8];
#pragma unroll
        for (int ni = 0; ni < 4; ++ni) {
            int c = n0 + wn * 32 + ni * 8 + t * 2;
            float2 bb = *reinterpret_cast<const float2*>(b_enc + c);
            push_cand(r0,     c,     acc[mi][ni][0] + bb.x, th0);
            push_cand(r0,     c + 1, acc[mi][ni][1] + bb.y, th0);
            push_cand(r0 + 8, c,     acc[mi][ni][2] + bb.x, th1);
            push_cand(r0 + 8, c + 1, acc[mi][ni][3] + bb.y, th1);
            __stcs(reinterpret_cast<float2*>(zout + (size_t)r0 * D_DICT + c), z2);
            __stcs(reinterpret_cast<float2*>(zout + (size_t)(r0 + 8) * D_DICT + c), z2);
        }
    }
}

// ---------------- narrow (top-64 by key) + exact fp32 recompute + warp top-32 ----------------
__global__ void __launch_bounds__(256) exact_kernel(const float* __restrict__ x,
                                                    const float* __restrict__ W,
                                                    const float* __restrict__ b_enc,
                                                    float* __restrict__ zout) {
    const int row = blockIdx.x, tid = threadIdx.x;
    const int lane = tid & 31, warp = tid >> 5;
    __shared__ float xs[D_MODEL];
    __shared__ unsigned skeys[CAND_CAP];
    __shared__ int hist[256];
    __shared__ int cidx[CAND2];
    __shared__ float cval[CAND2];
    __shared__ int ssel[TOPK];
    __shared__ int s_cut, s_scnt;

    reinterpret_cast<float4*>(xs)[tid] =
        reinterpret_cast<const float4*>(x + (size_t)row * D_MODEL)[tid];
    int cnt = min(g_cnt[row], CAND_CAP);
    hist[tid] = 0;
    if (tid == 0) s_scnt = 0;
    for (int i = tid; i < cnt; i += 256) skeys[i] = g_cand[row * CAND_CAP + i];
    __syncthreads();

    for (int i = tid; i < cnt; i += 256) {
        int bin = (int)((skeys[i] >> 16) - 0x4000u) >> 4;
        bin = max(0, min(bin, 255));
        atomicAdd(&hist[bin], 1);
    }
    __syncthreads();
#pragma unroll
    for (int off = 1; off < 256; off <<= 1) {
        int v = (tid + off < 256) ? hist[tid + off] : 0;
        __syncthreads();
        hist[tid] += v;
        __syncthreads();
    }
    int need = min(NARROW, cnt);
    if (hist[tid] >= need && (tid == 255 || hist[tid + 1] < need)) s_cut = tid;
    __syncthreads();
    int cut = s_cut;

    for (int i = tid; i < cnt; i += 256) {
        int bin = (int)((skeys[i] >> 16) - 0x4000u) >> 4;
        bin = max(0, min(bin, 255));
        if (bin >= cut) {
            int p = atomicAdd(&s_scnt, 1);
            if (p < CAND2) cidx[p] = (int)(skeys[i] & 0xFFFFu);
        }
    }
    __syncthreads();
    int cnt2 = min(s_scnt, CAND2);

    const float4* xs4 = reinterpret_cast<const float4*>(xs);
    for (int c = warp; c < cnt2; c += 8) {
        int f = cidx[c];
        const float4* w4 = reinterpret_cast<const float4*>(W + (size_t)f * D_MODEL);
        float a0 = 0.f, a1 = 0.f;
#pragma unroll
        for (int j = 0; j < 8; j += 2) {
            float4 wv = w4[lane + j * 32], xv = xs4[lane + j * 32];
            a0 += wv.x * xv.x; a0 += wv.y * xv.y; a0 += wv.z * xv.z; a0 += wv.w * xv.w;
            float4 wv2 = w4[lane + (j + 1) * 32], xv2 = xs4[lane + (j + 1) * 32];
            a1 += wv2.x * xv2.x; a1 += wv2.y * xv2.y; a1 += wv2.z * xv2.z; a1 += wv2.w * xv2.w;
        }
        float a = a0 + a1;
#pragma unroll
        for (int off = 16; off; off >>= 1) a += __shfl_down_sync(0xffffffffu, a, off);
        if (lane == 0) cval[c] = a + b_enc[f];
    }
    __syncthreads();

    if (warp == 0) {
        float v[5]; int id[5];
#pragma unroll
        for (int j = 0; j < 5; ++j) {
            int i = lane + j * 32;
            if (i < cnt2) { v[j] = fabsf(cval[i]); id[j] = i; }
            else          { v[j] = -1.f;           id[j] = -1; }
        }
        for (int it = 0; it < TOPK; ++it) {
            float mv = v[0]; int ms = 0;
#pragma unroll
            for (int j = 1; j < 5; ++j)
                if (v[j] > mv) { mv = v[j]; ms = j; }
            float bv = mv; int bl = lane;
#pragma unroll
            for (int off = 16; off; off >>= 1) {
                float ov = __shfl_xor_sync(0xffffffffu, bv, off);
                int   ol = __shfl_xor_sync(0xffffffffu, bl, off);
                if (ov > bv || (ov == bv && ol < bl)) { bv = ov; bl = ol; }
            }
            if (lane == bl) { ssel[it] = id[ms]; v[ms] = -1.f; }
        }
    }
    __syncthreads();

    if (tid < TOPK) {
        int s = ssel[tid];
        if (s >= 0) {
            int f = cidx[s]; float vv = cval[s];
            zout[(size_t)row * D_DICT + f] = vv;
            g_selidx[row * TOPK + tid] = f;
            g_selval[row * TOPK + tid] = vv;
        } else {
            g_selidx[row * TOPK + tid] = 0;
            g_selval[row * TOPK + tid] = 0.f;
        }
    }
}

// ---------------- sparse decoder (fp16 weights) ----------------
__global__ void decode_kernel(const float* __restrict__ b_dec, float* __restrict__ recon) {
    const int row = blockIdx.x, tid = threadIdx.x;
    __shared__ int sif[TOPK];
    __shared__ float sv[TOPK];
    if (tid < TOPK) { sif[tid] = g_selidx[row * TOPK + tid]; sv[tid] = g_selval[row * TOPK + tid]; }
    __syncthreads();
    float4 acc = reinterpret_cast<const float4*>(b_dec)[tid];
    const uint2* wt2 = reinterpret_cast<const uint2*>(g_wt);
#pragma unroll 4
    for (int s = 0; s < TOPK; ++s) {
        float v = sv[s]; int f = sif[s];
        uint2 w = wt2[(size_t)f * (D_MODEL / 4) + tid];
        float2 f01 = __half22float2(*reinterpret_cast<__half2*>(&w.x));
        float2 f23 = __half22float2(*reinterpret_cast<__half2*>(&w.y));
        acc.x += v * f01.x; acc.y += v * f01.y; acc.z += v * f23.x; acc.w += v * f23.y;
    }
    reinterpret_cast<float4*>(recon + (size_t)row * D_MODEL)[tid] = acc;
}

// ---------------- launch ----------------
extern "C" void kernel_launch(void* const* d_in, const int* in_sizes, int n_in,
                              void* d_out, int out_size) {
    const float* x     = (const float*)d_in[0];
    const float* W_enc = (const float*)d_in[1];
    const float* b_enc = (const float*)d_in[2];
    const float* W_dec = (const float*)d_in[3];
    const float* b_dec = (const float*)d_in[4];
    float* recon = (float*)d_out;
    float* zout  = recon + (size_t)NTOK * D_MODEL;

    const int GEMM_SMEM = 2 * (BM + BN) * BKPB;  // 73728 B
    cudaFuncSetAttribute(gemm_enc_kernel, cudaFuncAttributeMaxDynamicSharedMemorySize, GEMM_SMEM);

    rownorm_kernel<<<NTOK / 8, 256>>>(x);                                          // 1 (also resets g_cnt)
    cvtw_kernel<<<2048, 256>>>(reinterpret_cast<const float4*>(W_enc),
                               D_DICT * D_MODEL / 4);                              // 2
    transpose_kernel<<<dim3(D_DICT / 32, D_MODEL / 32), dim3(32, 8)>>>(W_dec);     // 3
    gemm_enc_kernel<<<dim3(D_DICT / BN, NTOK / BM), 256, GEMM_SMEM>>>(b_enc, zout);// 4 (zeros zout tile-wise)
    exact_kernel<<<NTOK, 256>>>(x, W_enc, b_enc, zout);                            // 5
    decode_kernel<<<NTOK, 256>>>(b_dec, recon);                                    // 6
}